// round 1
// baseline (speedup 1.0000x reference)
#include <cuda_runtime.h>

#define NN 50000
#define EE 800000
#define GF 256
#define HD 20
#define OD 128
#define DPB 8
#define SMEM_MAIN ((DPB*HD*OD + DPB*HD) * 4)

__device__ float g_h[NN * HD];
__device__ int g_counts[NN];
__device__ int g_offsets[NN + 1];
__device__ int g_cursor[NN];
__device__ int g_edge_src[EE];
__device__ int g_is64;

// ---------------------------------------------------------------------------
// Detect whether index tensors are int64 (odd 32-bit words all zero) or int32.
__global__ void k_detect(const int* __restrict__ dst_words) {
    __shared__ int any_nonzero;
    if (threadIdx.x == 0) any_nonzero = 0;
    __syncthreads();
    for (int i = threadIdx.x; i < 1024; i += blockDim.x) {
        if (dst_words[2 * i + 1] != 0) any_nonzero = 1;
    }
    __syncthreads();
    if (threadIdx.x == 0) g_is64 = any_nonzero ? 0 : 1;
}

__device__ __forceinline__ int load_idx(const void* p, int e, int is64) {
    if (is64) return (int)((const long long*)p)[e];
    return ((const int*)p)[e];
}

// ---------------------------------------------------------------------------
__global__ void k_zero() {
    int i = blockIdx.x * blockDim.x + threadIdx.x;
    if (i < NN) g_counts[i] = 0;
}

// ---------------------------------------------------------------------------
// h = ReLU(LN(node_feat @ W_node + b_node)) ; warp per node.
__global__ void k_node(const float* __restrict__ x, const float* __restrict__ W,
                       const float* __restrict__ b, const float* __restrict__ g,
                       const float* __restrict__ beta) {
    __shared__ float sm[8][GF];
    int w = threadIdx.x >> 5, lane = threadIdx.x & 31;
    int n = blockIdx.x * 8 + w;
    if (n >= NN) return;

    const float* row = x + (size_t)n * GF;
    for (int c = lane; c < GF; c += 32) sm[w][c] = row[c];
    __syncwarp();

    float acc = 0.f;
    if (lane < HD) {
        acc = b[lane];
#pragma unroll 8
        for (int c = 0; c < GF; c++) acc = fmaf(sm[w][c], W[c * HD + lane], acc);
    }
    float v = (lane < HD) ? acc : 0.f;
    float s = v, s2 = v * v;
#pragma unroll
    for (int o = 16; o; o >>= 1) {
        s += __shfl_xor_sync(0xffffffffu, s, o);
        s2 += __shfl_xor_sync(0xffffffffu, s2, o);
    }
    float mu = s * (1.f / HD);
    float var = s2 * (1.f / HD) - mu * mu;
    float r = rsqrtf(var + 1e-5f);
    if (lane < HD) {
        float y = (acc - mu) * r * g[lane] + beta[lane];
        g_h[n * HD + lane] = fmaxf(y, 0.f);
    }
}

// ---------------------------------------------------------------------------
__global__ void k_hist(const void* __restrict__ dst) {
    int e = blockIdx.x * blockDim.x + threadIdx.x;
    int is64 = g_is64;
    if (e < EE) atomicAdd(&g_counts[load_idx(dst, e, is64)], 1);
}

// Single-block exclusive scan over g_counts (Hillis-Steele per 1024 chunk).
__global__ void k_scan() {
    __shared__ int sd[1024];
    int tid = threadIdx.x;
    int carry = 0;
    for (int base = 0; base < NN; base += 1024) {
        int idx = base + tid;
        int v = (idx < NN) ? g_counts[idx] : 0;
        sd[tid] = v;
        __syncthreads();
        for (int off = 1; off < 1024; off <<= 1) {
            int t = (tid >= off) ? sd[tid - off] : 0;
            __syncthreads();
            sd[tid] += t;
            __syncthreads();
        }
        int excl = carry + sd[tid] - v;
        if (idx < NN) { g_offsets[idx] = excl; g_cursor[idx] = excl; }
        int tot = sd[1023];
        carry += tot;
        __syncthreads();
    }
    if (tid == 0) g_offsets[NN] = carry;
}

__global__ void k_scatter(const void* __restrict__ src, const void* __restrict__ dst) {
    int e = blockIdx.x * blockDim.x + threadIdx.x;
    int is64 = g_is64;
    if (e < EE) {
        int d = load_idx(dst, e, is64);
        int pos = atomicAdd(&g_cursor[d], 1);
        g_edge_src[pos] = load_idx(src, e, is64);
    }
}

// ---------------------------------------------------------------------------
// Main fused kernel: per block, 8 dsts. Phase 1 builds T[d][i][j] = sum_k
// h[dst_d][k] * W_kron[(i*20+k), j] in smem. Phase 2: warp d streams dst_d's
// edges: y[j] = sum_i h[src][i] * T[d][i][j], LN+ReLU via warp shuffles,
// accumulate, single float4 store per lane. No atomics, no per-edge barriers.
__global__ void k_main(const float* __restrict__ Wk, const float* __restrict__ bk,
                       const float* __restrict__ gk, const float* __restrict__ betak,
                       float* __restrict__ out) {
    extern __shared__ float smem[];
    float* T_s = smem;                  // DPB * HD * OD
    float* b_s = smem + DPB * HD * OD;  // DPB * HD

    int tid = threadIdx.x;
    int dst0 = blockIdx.x * DPB;

    for (int t = tid; t < DPB * HD; t += 256) {
        b_s[t] = g_h[(dst0 + t / HD) * HD + (t % HD)];
    }
    __syncthreads();

    // Phase 1: 256 threads; thread = (half, j). half covers i in [half*10, half*10+10).
    {
        int j = tid & 127, half = tid >> 7;
#pragma unroll 1
        for (int ii = 0; ii < 10; ii++) {
            int i = half * 10 + ii;
            float w[HD];
#pragma unroll
            for (int k = 0; k < HD; k++) w[k] = Wk[(i * HD + k) * OD + j];
#pragma unroll
            for (int d = 0; d < DPB; d++) {
                float acc = 0.f;
#pragma unroll
                for (int k = 0; k < HD; k++) acc = fmaf(b_s[d * HD + k], w[k], acc);
                T_s[(d * HD + i) * OD + j] = acc;
            }
        }
    }
    __syncthreads();

    // Phase 2: warp per dst; lane owns columns [4*lane, 4*lane+4).
    int warp = tid >> 5, lane = tid & 31;
    int dd = dst0 + warp;
    const float* Td = T_s + warp * HD * OD;

    float4 bk4 = *(const float4*)(bk + 4 * lane);
    float4 gk4 = *(const float4*)(gk + 4 * lane);
    float4 bt4 = *(const float4*)(betak + 4 * lane);

    int e0 = g_offsets[dd], e1 = g_offsets[dd + 1];
    float a0 = 0.f, a1 = 0.f, a2 = 0.f, a3 = 0.f;

    float acur = 0.f, anx = 0.f;
    if (e0 < e1 && lane < HD) acur = g_h[g_edge_src[e0] * HD + lane];

    for (int e = e0; e < e1; e++) {
        if (e + 1 < e1 && lane < HD) anx = g_h[g_edge_src[e + 1] * HD + lane];

        float y0 = bk4.x, y1 = bk4.y, y2 = bk4.z, y3 = bk4.w;
#pragma unroll
        for (int i = 0; i < HD; i++) {
            float ai = __shfl_sync(0xffffffffu, acur, i);
            float4 t4 = *(const float4*)(Td + i * OD + 4 * lane);
            y0 = fmaf(ai, t4.x, y0);
            y1 = fmaf(ai, t4.y, y1);
            y2 = fmaf(ai, t4.z, y2);
            y3 = fmaf(ai, t4.w, y3);
        }
        // LayerNorm across the 128 outputs (warp-local: 4 values per lane).
        float s = y0 + y1 + y2 + y3;
        float s2 = y0 * y0 + y1 * y1 + y2 * y2 + y3 * y3;
#pragma unroll
        for (int o = 16; o; o >>= 1) {
            s += __shfl_xor_sync(0xffffffffu, s, o);
            s2 += __shfl_xor_sync(0xffffffffu, s2, o);
        }
        float mu = s * (1.f / OD);
        float var = fmaf(-mu, mu, s2 * (1.f / OD));
        float r = rsqrtf(var + 1e-5f);

        a0 += fmaxf(fmaf((y0 - mu) * r, gk4.x, bt4.x), 0.f);
        a1 += fmaxf(fmaf((y1 - mu) * r, gk4.y, bt4.y), 0.f);
        a2 += fmaxf(fmaf((y2 - mu) * r, gk4.z, bt4.z), 0.f);
        a3 += fmaxf(fmaf((y3 - mu) * r, gk4.w, bt4.w), 0.f);

        acur = anx;
    }

    *(float4*)(out + (size_t)dd * OD + 4 * lane) = make_float4(a0, a1, a2, a3);
}

// ---------------------------------------------------------------------------
extern "C" void kernel_launch(void* const* d_in, const int* in_sizes, int n_in,
                              void* d_out, int out_size) {
    const float* node_feat = (const float*)d_in[0];
    const float* W_node    = (const float*)d_in[1];
    const float* b_node    = (const float*)d_in[2];
    const float* g_node    = (const float*)d_in[3];
    const float* beta_node = (const float*)d_in[4];
    const float* W_kron    = (const float*)d_in[5];
    const float* b_kron    = (const float*)d_in[6];
    const float* g_kron    = (const float*)d_in[7];
    const float* beta_kron = (const float*)d_in[8];
    const void*  src       = (const void*)d_in[9];
    const void*  dst       = (const void*)d_in[10];
    float* out = (float*)d_out;

    cudaFuncSetAttribute(k_main, cudaFuncAttributeMaxDynamicSharedMemorySize, SMEM_MAIN);

    k_detect<<<1, 256>>>((const int*)dst);
    k_zero<<<(NN + 255) / 256, 256>>>();
    k_node<<<(NN + 7) / 8, 256>>>(node_feat, W_node, b_node, g_node, beta_node);
    k_hist<<<(EE + 255) / 256, 256>>>(dst);
    k_scan<<<1, 1024>>>();
    k_scatter<<<(EE + 255) / 256, 256>>>(src, dst);
    k_main<<<NN / DPB, 256, SMEM_MAIN>>>(W_kron, b_kron, g_kron, beta_kron, out);
}

// round 2
// speedup vs baseline: 1.0001x; 1.0001x over previous
#include <cuda_runtime.h>

#define NN 50000
#define EE 800000
#define GF 256
#define HD 20
#define OD 128
#define DPB 8
#define SMEM_MAIN ((DPB*HD*OD + DPB*HD) * 4)

__device__ float g_h[NN * HD];
__device__ int g_counts[NN];
__device__ int g_offsets[NN + 1];
__device__ int g_cursor[NN];
__device__ int g_edge_src[EE];
__device__ int g_is64;

// ---------------------------------------------------------------------------
// Detect whether index tensors are int64 (odd 32-bit words all zero) or int32.
__global__ void k_detect(const int* __restrict__ dst_words) {
    __shared__ int any_nonzero;
    if (threadIdx.x == 0) any_nonzero = 0;
    __syncthreads();
    for (int i = threadIdx.x; i < 1024; i += blockDim.x) {
        if (dst_words[2 * i + 1] != 0) any_nonzero = 1;
    }
    __syncthreads();
    if (threadIdx.x == 0) g_is64 = any_nonzero ? 0 : 1;
}

__device__ __forceinline__ int load_idx(const void* p, int e, int is64) {
    if (is64) return (int)((const long long*)p)[e];
    return ((const int*)p)[e];
}

// ---------------------------------------------------------------------------
__global__ void k_zero() {
    int i = blockIdx.x * blockDim.x + threadIdx.x;
    if (i < NN) g_counts[i] = 0;
}

// ---------------------------------------------------------------------------
// h = ReLU(LN(node_feat @ W_node + b_node)) ; warp per node.
__global__ void k_node(const float* __restrict__ x, const float* __restrict__ W,
                       const float* __restrict__ b, const float* __restrict__ g,
                       const float* __restrict__ beta) {
    __shared__ float sm[8][GF];
    int w = threadIdx.x >> 5, lane = threadIdx.x & 31;
    int n = blockIdx.x * 8 + w;
    if (n >= NN) return;

    const float* row = x + (size_t)n * GF;
    for (int c = lane; c < GF; c += 32) sm[w][c] = row[c];
    __syncwarp();

    float acc = 0.f;
    if (lane < HD) {
        acc = b[lane];
#pragma unroll 8
        for (int c = 0; c < GF; c++) acc = fmaf(sm[w][c], W[c * HD + lane], acc);
    }
    float v = (lane < HD) ? acc : 0.f;
    float s = v, s2 = v * v;
#pragma unroll
    for (int o = 16; o; o >>= 1) {
        s += __shfl_xor_sync(0xffffffffu, s, o);
        s2 += __shfl_xor_sync(0xffffffffu, s2, o);
    }
    float mu = s * (1.f / HD);
    float var = s2 * (1.f / HD) - mu * mu;
    float r = rsqrtf(var + 1e-5f);
    if (lane < HD) {
        float y = (acc - mu) * r * g[lane] + beta[lane];
        g_h[n * HD + lane] = fmaxf(y, 0.f);
    }
}

// ---------------------------------------------------------------------------
__global__ void k_hist(const void* __restrict__ dst) {
    int e = blockIdx.x * blockDim.x + threadIdx.x;
    int is64 = g_is64;
    if (e < EE) atomicAdd(&g_counts[load_idx(dst, e, is64)], 1);
}

// Single-block exclusive scan over g_counts (Hillis-Steele per 1024 chunk).
__global__ void k_scan() {
    __shared__ int sd[1024];
    int tid = threadIdx.x;
    int carry = 0;
    for (int base = 0; base < NN; base += 1024) {
        int idx = base + tid;
        int v = (idx < NN) ? g_counts[idx] : 0;
        sd[tid] = v;
        __syncthreads();
        for (int off = 1; off < 1024; off <<= 1) {
            int t = (tid >= off) ? sd[tid - off] : 0;
            __syncthreads();
            sd[tid] += t;
            __syncthreads();
        }
        int excl = carry + sd[tid] - v;
        if (idx < NN) { g_offsets[idx] = excl; g_cursor[idx] = excl; }
        int tot = sd[1023];
        carry += tot;
        __syncthreads();
    }
    if (tid == 0) g_offsets[NN] = carry;
}

__global__ void k_scatter(const void* __restrict__ src, const void* __restrict__ dst) {
    int e = blockIdx.x * blockDim.x + threadIdx.x;
    int is64 = g_is64;
    if (e < EE) {
        int d = load_idx(dst, e, is64);
        int pos = atomicAdd(&g_cursor[d], 1);
        g_edge_src[pos] = load_idx(src, e, is64);
    }
}

// ---------------------------------------------------------------------------
// Main fused kernel: per block, 8 dsts. Phase 1 builds T[d][i][j] = sum_k
// h[dst_d][k] * W_kron[(i*20+k), j] in smem. Phase 2: warp d streams dst_d's
// edges: y[j] = sum_i h[src][i] * T[d][i][j], LN+ReLU via warp shuffles,
// accumulate, single float4 store per lane. No atomics, no per-edge barriers.
__global__ void k_main(const float* __restrict__ Wk, const float* __restrict__ bk,
                       const float* __restrict__ gk, const float* __restrict__ betak,
                       float* __restrict__ out) {
    extern __shared__ float smem[];
    float* T_s = smem;                  // DPB * HD * OD
    float* b_s = smem + DPB * HD * OD;  // DPB * HD

    int tid = threadIdx.x;
    int dst0 = blockIdx.x * DPB;

    for (int t = tid; t < DPB * HD; t += 256) {
        b_s[t] = g_h[(dst0 + t / HD) * HD + (t % HD)];
    }
    __syncthreads();

    // Phase 1: 256 threads; thread = (half, j). half covers i in [half*10, half*10+10).
    {
        int j = tid & 127, half = tid >> 7;
#pragma unroll 1
        for (int ii = 0; ii < 10; ii++) {
            int i = half * 10 + ii;
            float w[HD];
#pragma unroll
            for (int k = 0; k < HD; k++) w[k] = Wk[(i * HD + k) * OD + j];
#pragma unroll
            for (int d = 0; d < DPB; d++) {
                float acc = 0.f;
#pragma unroll
                for (int k = 0; k < HD; k++) acc = fmaf(b_s[d * HD + k], w[k], acc);
                T_s[(d * HD + i) * OD + j] = acc;
            }
        }
    }
    __syncthreads();

    // Phase 2: warp per dst; lane owns columns [4*lane, 4*lane+4).
    int warp = tid >> 5, lane = tid & 31;
    int dd = dst0 + warp;
    const float* Td = T_s + warp * HD * OD;

    float4 bk4 = *(const float4*)(bk + 4 * lane);
    float4 gk4 = *(const float4*)(gk + 4 * lane);
    float4 bt4 = *(const float4*)(betak + 4 * lane);

    int e0 = g_offsets[dd], e1 = g_offsets[dd + 1];
    float a0 = 0.f, a1 = 0.f, a2 = 0.f, a3 = 0.f;

    float acur = 0.f, anx = 0.f;
    if (e0 < e1 && lane < HD) acur = g_h[g_edge_src[e0] * HD + lane];

    for (int e = e0; e < e1; e++) {
        if (e + 1 < e1 && lane < HD) anx = g_h[g_edge_src[e + 1] * HD + lane];

        float y0 = bk4.x, y1 = bk4.y, y2 = bk4.z, y3 = bk4.w;
#pragma unroll
        for (int i = 0; i < HD; i++) {
            float ai = __shfl_sync(0xffffffffu, acur, i);
            float4 t4 = *(const float4*)(Td + i * OD + 4 * lane);
            y0 = fmaf(ai, t4.x, y0);
            y1 = fmaf(ai, t4.y, y1);
            y2 = fmaf(ai, t4.z, y2);
            y3 = fmaf(ai, t4.w, y3);
        }
        // LayerNorm across the 128 outputs (warp-local: 4 values per lane).
        float s = y0 + y1 + y2 + y3;
        float s2 = y0 * y0 + y1 * y1 + y2 * y2 + y3 * y3;
#pragma unroll
        for (int o = 16; o; o >>= 1) {
            s += __shfl_xor_sync(0xffffffffu, s, o);
            s2 += __shfl_xor_sync(0xffffffffu, s2, o);
        }
        float mu = s * (1.f / OD);
        float var = fmaf(-mu, mu, s2 * (1.f / OD));
        float r = rsqrtf(var + 1e-5f);

        a0 += fmaxf(fmaf((y0 - mu) * r, gk4.x, bt4.x), 0.f);
        a1 += fmaxf(fmaf((y1 - mu) * r, gk4.y, bt4.y), 0.f);
        a2 += fmaxf(fmaf((y2 - mu) * r, gk4.z, bt4.z), 0.f);
        a3 += fmaxf(fmaf((y3 - mu) * r, gk4.w, bt4.w), 0.f);

        acur = anx;
    }

    *(float4*)(out + (size_t)dd * OD + 4 * lane) = make_float4(a0, a1, a2, a3);
}

// ---------------------------------------------------------------------------
extern "C" void kernel_launch(void* const* d_in, const int* in_sizes, int n_in,
                              void* d_out, int out_size) {
    const float* node_feat = (const float*)d_in[0];
    const float* W_node    = (const float*)d_in[1];
    const float* b_node    = (const float*)d_in[2];
    const float* g_node    = (const float*)d_in[3];
    const float* beta_node = (const float*)d_in[4];
    const float* W_kron    = (const float*)d_in[5];
    const float* b_kron    = (const float*)d_in[6];
    const float* g_kron    = (const float*)d_in[7];
    const float* beta_kron = (const float*)d_in[8];
    const void*  src       = (const void*)d_in[9];
    const void*  dst       = (const void*)d_in[10];
    float* out = (float*)d_out;

    cudaFuncSetAttribute(k_main, cudaFuncAttributeMaxDynamicSharedMemorySize, SMEM_MAIN);

    k_detect<<<1, 256>>>((const int*)dst);
    k_zero<<<(NN + 255) / 256, 256>>>();
    k_node<<<(NN + 7) / 8, 256>>>(node_feat, W_node, b_node, g_node, beta_node);
    k_hist<<<(EE + 255) / 256, 256>>>(dst);
    k_scan<<<1, 1024>>>();
    k_scatter<<<(EE + 255) / 256, 256>>>(src, dst);
    k_main<<<NN / DPB, 256, SMEM_MAIN>>>(W_kron, b_kron, g_kron, beta_kron, out);
}